// round 15
// baseline (speedup 1.0000x reference)
#include <cuda_runtime.h>
#include <cuda_fp16.h>
#include <cstdint>
#include <cstddef>

// ResidualVectorQuantizer via warp-level fp16 MMA, 3-term exact-enough fp32 GEMM.
// R15: R14 fixed (RED region was 256 doubles, 512 threads stored -> OOB smem).
//      TM=512, 1 block/SM; ALL 4 layers' codebooks resident in smem; layer loop
//      has zero block barriers and zero staging; warps free-run.
// N x D points, L layers of NE codes (D=32, NE=256, L=4).
// Out (float32): x_q [N*D], mean_loss [1], indices [N*L].

#define DD   32
#define NEC  256
#define LL   4
#define TM   512
#define RVQ_BETA 0.25f
#define MAXBLK_P 8192

// ---- global scratch ----
__device__ uint32_t g_bp[LL * NEC * 32];
__device__ float    g_cn[LL * NEC];          // 0.5*||c||^2
__device__ float    g_part[MAXBLK_P * LL];
__device__ unsigned g_ctr;

// ---- smem map (bytes) ----
#define OFF_B    0          // ALL layers: 4 * 256 codes * 128B swizzled = 131072
#define OFF_CN   131072     // 4096 (all layers cn, fp32)
#define OFF_AR   135168     // A/R rows: 512 * 144 = 73728
#define OFF_ARG  208896     // 2048 (512 ints)
#define OFF_RED  210944     // 4096 (512 doubles for final reduce; 64 floats for warp sums)
#define OFF_FLAG 215040     // 4
#define SMEM_BYTES 215168

__device__ __forceinline__ uint32_t packh2(__half a, __half b) {
    __half2 h = __halves2half2(a, b);
    return *(uint32_t*)&h;
}
__device__ __forceinline__ void sp16(float v, __half& h, __half& l) {
    h = __float2half_rn(v);
    l = __float2half_rn(v - __half2float(h));
}
__device__ __forceinline__ uint32_t smem_u32(const void* p) {
    uint32_t a;
    asm("{ .reg .u64 t; cvta.to.shared.u64 t, %1; cvt.u32.u64 %0, t; }" : "=r"(a) : "l"(p));
    return a;
}
__device__ __forceinline__ void cpasync16(uint32_t dst, const void* src) {
    asm volatile("cp.async.cg.shared.global [%0], [%1], 16;" :: "r"(dst), "l"(src));
}
#define CP_COMMIT() asm volatile("cp.async.commit_group;" ::: "memory")
#define CP_WAIT0()  asm volatile("cp.async.wait_group 0;" ::: "memory")

#define MMA16(C, A0, A1, A2, A3, B0, B1) \
    asm volatile("mma.sync.aligned.m16n8k16.row.col.f32.f16.f16.f32 " \
        "{%0,%1,%2,%3}, {%4,%5,%6,%7}, {%8,%9}, {%0,%1,%2,%3};" \
        : "+f"((C)[0]), "+f"((C)[1]), "+f"((C)[2]), "+f"((C)[3]) \
        : "r"(A0), "r"(A1), "r"(A2), "r"(A3), "r"(B0), "r"(B1))

// ---------------- prep ----------------
__global__ void rvq_prep(const float* __restrict__ cb) {
    int e = blockIdx.x * blockDim.x + threadIdx.x;
    if (e >= LL * NEC) return;
    const float* row = cb + (size_t)e * DD;
    __half h[DD], lo[DD];
    float cn = 0.f;
    #pragma unroll
    for (int k = 0; k < DD; k++) {
        float v = row[k];
        sp16(v, h[k], lo[k]);
        cn = fmaf(v, v, cn);
    }
    g_cn[e] = 0.5f * cn;
    uint32_t* dst = g_bp + (size_t)e * 32;
    #pragma unroll
    for (int kk = 0; kk < 4; kk++) {
        dst[8*kk + 0] = packh2(h[2*kk],       h[2*kk + 1]);
        dst[8*kk + 1] = packh2(h[2*kk + 8],   h[2*kk + 9]);
        dst[8*kk + 2] = packh2(h[16 + 2*kk],  h[16 + 2*kk + 1]);
        dst[8*kk + 3] = packh2(h[24 + 2*kk],  h[24 + 2*kk + 1]);
        dst[8*kk + 4] = packh2(lo[2*kk],      lo[2*kk + 1]);
        dst[8*kk + 5] = packh2(lo[2*kk + 8],  lo[2*kk + 9]);
        dst[8*kk + 6] = packh2(lo[16 + 2*kk], lo[16 + 2*kk + 1]);
        dst[8*kk + 7] = packh2(lo[24 + 2*kk], lo[24 + 2*kk + 1]);
    }
}

// ---------------- main ----------------
__global__ void __launch_bounds__(TM, 1) rvq_mma_kernel(
    const float* __restrict__ x, const float* __restrict__ cb,
    float* __restrict__ out, int N, int has_loss, int has_idx, int nblk)
{
    extern __shared__ char smem[];
    const uint32_t sbase = smem_u32(smem);
    const int tid = threadIdx.x;
    const int w = tid >> 5;
    const int lane = tid & 31;
    const int q = lane >> 2;
    const int kk = lane & 3;
    const int p = blockIdx.x * TM + tid;
    const bool active = (p < N);

    char* arow = smem + OFF_AR + (size_t)tid * 144;   // this thread's A/R row

    // ---- stage ALL layers' B (8192 x 16B) + cn (4096B) via cp.async ----
    {
        const char* src = (const char*)g_bp;
        #pragma unroll
        for (int i = tid; i < 8192; i += TM) {        // 16 per thread
            int lcode = i >> 3, c = i & 7;
            cpasync16(sbase + OFF_B + lcode * 128 + ((c ^ (lcode & 7)) * 16),
                      src + (size_t)i * 16);
        }
        if (tid < 256) cpasync16(sbase + OFF_CN + tid * 16, (const char*)g_cn + (size_t)tid * 16);
        CP_COMMIT();
    }

    // ---- init residual rows from x (overlaps B staging) ----
    {
        float4* rp = (float4*)arow;
        if (active) {
            const float4* xr = (const float4*)(x + (size_t)p * DD);
            #pragma unroll
            for (int j = 0; j < 8; j++) rp[j] = xr[j];
        } else {
            float4 z = make_float4(0.f, 0.f, 0.f, 0.f);
            #pragma unroll
            for (int j = 0; j < 8; j++) rp[j] = z;
        }
    }

    CP_WAIT0();
    __syncthreads();   // B + cn resident for the WHOLE kernel

    const uint32_t bhRel = (uint32_t)q * 128 + (uint32_t)(((2*kk)     ^ q) * 16);
    const uint32_t blRel = (uint32_t)q * 128 + (uint32_t)(((2*kk + 1) ^ q) * 16);

    float tl[LL];
    int bia[LL];

    for (int l = 0; l < LL; l++) {
        const char* Bl = smem + OFF_B + (size_t)l * 32768;
        const char* CNl = smem + OFF_CN + (size_t)l * 1024;

        // ---- (1) read residual; (2) split -> overwrite own row ----
        float t[DD];
        {
            const float4* rp = (const float4*)arow;
            #pragma unroll
            for (int j = 0; j < 8; j++) {
                float4 v = rp[j];
                t[4*j] = v.x; t[4*j+1] = v.y; t[4*j+2] = v.z; t[4*j+3] = v.w;
            }
        }
        #pragma unroll
        for (int c4 = 0; c4 < 4; c4++) {
            __half h0,l0,h1,l1,h2,l2,h3,l3,h4,l4,h5,l5,h6,l6,h7,l7;
            sp16(-t[2*c4],        h0, l0); sp16(-t[2*c4 + 1],      h1, l1);
            sp16(-t[2*c4 + 8],    h2, l2); sp16(-t[2*c4 + 9],      h3, l3);
            sp16(-t[16 + 2*c4],   h4, l4); sp16(-t[16 + 2*c4 + 1], h5, l5);
            sp16(-t[24 + 2*c4],   h6, l6); sp16(-t[24 + 2*c4 + 1], h7, l7);
            *(uint4*)(arow + c4 * 16)      = make_uint4(packh2(h0,h1), packh2(h2,h3), packh2(h4,h5), packh2(h6,h7));
            *(uint4*)(arow + 64 + c4 * 16) = make_uint4(packh2(l0,l1), packh2(l2,l3), packh2(l4,l5), packh2(l6,l7));
        }
        __syncwarp();      // warp's split rows visible

        // ---- (3) A fragments (warp-local rows) ----
        uint4 U0h[2], U1h[2], U0l[2], U1l[2];
        {
            const char* ab = smem + OFF_AR + (size_t)(w * 32 + q) * 144 + kk * 16;
            #pragma unroll
            for (int m = 0; m < 2; m++) {
                U0h[m] = *(const uint4*)(ab + (m * 16) * 144);
                U1h[m] = *(const uint4*)(ab + (m * 16 + 8) * 144);
                U0l[m] = *(const uint4*)(ab + (m * 16) * 144 + 64);
                U1l[m] = *(const uint4*)(ab + (m * 16 + 8) * 144 + 64);
            }
        }
        __syncwarp();      // frag loads done -> rows reusable

        // ---- (4) park residual fp32 back into the row ----
        {
            float4* rp = (float4*)arow;
            #pragma unroll
            for (int j = 0; j < 8; j++)
                rp[j] = make_float4(t[4*j], t[4*j+1], t[4*j+2], t[4*j+3]);
        }

        // ---- (5) compute: one uninterrupted pass over 32 n-tiles ----
        float best[4];
        int bidx[4];
        #pragma unroll
        for (int j = 0; j < 4; j++) { best[j] = 3.402823466e38f; bidx[j] = 0; }

        #pragma unroll 2
        for (int nt2 = 0; nt2 < 16; nt2++) {
            const char* p0 = Bl + (size_t)nt2 * 2048;
            uint4 BH0 = *(const uint4*)(p0 + bhRel);
            uint4 BL0 = *(const uint4*)(p0 + blRel);
            uint4 BH1 = *(const uint4*)(p0 + 1024 + bhRel);
            uint4 BL1 = *(const uint4*)(p0 + 1024 + blRel);
            float2 cn0 = *(const float2*)(CNl + (size_t)(nt2 * 16 + kk * 2) * 4);
            float2 cn1 = *(const float2*)(CNl + (size_t)(nt2 * 16 + 8 + kk * 2) * 4);

            float C0[2][4], C1[2][4];
            #pragma unroll
            for (int m = 0; m < 2; m++) {
                C0[m][0] = cn0.x; C0[m][1] = cn0.y; C0[m][2] = cn0.x; C0[m][3] = cn0.y;
                C1[m][0] = cn1.x; C1[m][1] = cn1.y; C1[m][2] = cn1.x; C1[m][3] = cn1.y;
            }
            #pragma unroll
            for (int m = 0; m < 2; m++) {
                MMA16(C0[m], U0h[m].x, U1h[m].x, U0h[m].y, U1h[m].y, BH0.x, BH0.y);
                MMA16(C1[m], U0h[m].x, U1h[m].x, U0h[m].y, U1h[m].y, BH1.x, BH1.y);
            }
            #pragma unroll
            for (int m = 0; m < 2; m++) {
                MMA16(C0[m], U0h[m].z, U1h[m].z, U0h[m].w, U1h[m].w, BH0.z, BH0.w);
                MMA16(C1[m], U0h[m].z, U1h[m].z, U0h[m].w, U1h[m].w, BH1.z, BH1.w);
            }
            #pragma unroll
            for (int m = 0; m < 2; m++) {
                MMA16(C0[m], U0l[m].x, U1l[m].x, U0l[m].y, U1l[m].y, BH0.x, BH0.y);
                MMA16(C1[m], U0l[m].x, U1l[m].x, U0l[m].y, U1l[m].y, BH1.x, BH1.y);
            }
            #pragma unroll
            for (int m = 0; m < 2; m++) {
                MMA16(C0[m], U0l[m].z, U1l[m].z, U0l[m].w, U1l[m].w, BH0.z, BH0.w);
                MMA16(C1[m], U0l[m].z, U1l[m].z, U0l[m].w, U1l[m].w, BH1.z, BH1.w);
            }
            #pragma unroll
            for (int m = 0; m < 2; m++) {
                MMA16(C0[m], U0h[m].x, U1h[m].x, U0h[m].y, U1h[m].y, BL0.x, BL0.y);
                MMA16(C1[m], U0h[m].x, U1h[m].x, U0h[m].y, U1h[m].y, BL1.x, BL1.y);
            }
            #pragma unroll
            for (int m = 0; m < 2; m++) {
                MMA16(C0[m], U0h[m].z, U1h[m].z, U0h[m].w, U1h[m].w, BL0.z, BL0.w);
                MMA16(C1[m], U0h[m].z, U1h[m].z, U0h[m].w, U1h[m].w, BL1.z, BL1.w);
            }

            int nb0 = (nt2 * 16) + kk * 2;
            int nb1 = nb0 + 8;
            #pragma unroll
            for (int m = 0; m < 2; m++)
                #pragma unroll
                for (int hi = 0; hi < 2; hi++) {
                    int jj = m * 2 + hi;
                    {
                        float c0 = C0[m][hi*2], c1 = C0[m][hi*2 + 1];
                        float mn = fminf(c0, c1);
                        int cand = (c1 < c0) ? (nb0 + 1) : nb0;
                        bidx[jj] = (mn < best[jj]) ? cand : bidx[jj];
                        best[jj] = fminf(best[jj], mn);
                    }
                    {
                        float c0 = C1[m][hi*2], c1 = C1[m][hi*2 + 1];
                        float mn = fminf(c0, c1);
                        int cand = (c1 < c0) ? (nb1 + 1) : nb1;
                        bidx[jj] = (mn < best[jj]) ? cand : bidx[jj];
                        best[jj] = fminf(best[jj], mn);
                    }
                }
        }

        // ---- (6) argmin reduce across the 4 kk-lanes of each group ----
        #pragma unroll
        for (int jj = 0; jj < 4; jj++) {
            #pragma unroll
            for (int ofs = 1; ofs <= 2; ofs <<= 1) {
                float ob = __shfl_xor_sync(0xffffffffu, best[jj], ofs);
                int oi = __shfl_xor_sync(0xffffffffu, bidx[jj], ofs);
                if (ob < best[jj] || (ob == best[jj] && oi < bidx[jj])) {
                    best[jj] = ob; bidx[jj] = oi;
                }
            }
        }
        int* argb = (int*)(smem + OFF_ARG);
        if (kk == 0) {
            #pragma unroll
            for (int jj = 0; jj < 4; jj++)
                argb[w * 32 + (jj >> 1) * 16 + (jj & 1) * 8 + q] = bidx[jj];
        }
        __syncwarp();
        int bi = argb[w * 32 + lane];
        bia[l] = bi;

        // ---- (7) residual update + loss; code gathered from resident B (c = h+l) ----
        {
            const char* crow = Bl + (size_t)bi * 128;
            const int sw = bi & 7;
            float r[DD];
            {
                const float4* rp = (const float4*)arow;
                #pragma unroll
                for (int j = 0; j < 8; j++) {
                    float4 v = rp[j];
                    r[4*j] = v.x; r[4*j+1] = v.y; r[4*j+2] = v.z; r[4*j+3] = v.w;
                }
            }
            float ls = 0.f;
            #pragma unroll
            for (int kkc = 0; kkc < 4; kkc++) {
                uint4 H = *(const uint4*)(crow + (((2*kkc)     ^ sw) * 16));
                uint4 L = *(const uint4*)(crow + (((2*kkc + 1) ^ sw) * 16));
                const uint32_t hw[4] = {H.x, H.y, H.z, H.w};
                const uint32_t lw[4] = {L.x, L.y, L.z, L.w};
                const int baseix[4] = {2*kkc, 2*kkc + 8, 16 + 2*kkc, 24 + 2*kkc};
                #pragma unroll
                for (int t2 = 0; t2 < 4; t2++) {
                    float2 hf = __half22float2(*(const __half2*)&hw[t2]);
                    float2 lf = __half22float2(*(const __half2*)&lw[t2]);
                    float cx = hf.x + lf.x;     // B stores splits of +c
                    float cy = hf.y + lf.y;
                    int b0 = baseix[t2];
                    float t0, xres;
                    t0 = cx - r[b0];     ls = fmaf(t0, t0, ls); xres = r[b0]     + t0; r[b0]     = r[b0]     - xres;
                    t0 = cy - r[b0 + 1]; ls = fmaf(t0, t0, ls); xres = r[b0 + 1] + t0; r[b0 + 1] = r[b0 + 1] - xres;
                }
            }
            {
                float4* rp = (float4*)arow;
                #pragma unroll
                for (int j = 0; j < 8; j++)
                    rp[j] = make_float4(r[4*j], r[4*j+1], r[4*j+2], r[4*j+3]);
            }
            tl[l] = active ? ls : 0.f;
        }
    }

    // ---- outputs ----
    if (active) {
        const float4* xr = (const float4*)(x + (size_t)p * DD);
        float4* qo = (float4*)(out + (size_t)p * DD);
        const float4* rp = (const float4*)arow;
        #pragma unroll
        for (int j = 0; j < 8; j++) {
            float4 v = xr[j];
            float4 rv = rp[j];
            float4 qv;
            qv.x = v.x - rv.x; qv.y = v.y - rv.y;
            qv.z = v.z - rv.z; qv.w = v.w - rv.w;
            qo[j] = qv;
        }
        if (has_idx) {
            float* oi = out + (size_t)N * DD + (has_loss ? 1 : 0) + (size_t)p * LL;
            #pragma unroll
            for (int l = 0; l < LL; l++) oi[l] = (float)bia[l];
        }
    }

    // ---- per-block loss partials: warp shuffle reduce (deterministic order) ----
    {
        float* wsum = (float*)(smem + OFF_RED);     // 64 floats (within 4096B region)
        #pragma unroll
        for (int l = 0; l < LL; l++) {
            float v = tl[l];
            v += __shfl_xor_sync(0xffffffffu, v, 16);
            v += __shfl_xor_sync(0xffffffffu, v, 8);
            v += __shfl_xor_sync(0xffffffffu, v, 4);
            v += __shfl_xor_sync(0xffffffffu, v, 2);
            v += __shfl_xor_sync(0xffffffffu, v, 1);
            if (lane == 0) wsum[w * LL + l] = v;
        }
        __syncthreads();
        if (tid < LL) {
            float s = 0.f;
            #pragma unroll
            for (int ww = 0; ww < TM / 32; ww++) s += wsum[ww * LL + tid];
            g_part[(size_t)blockIdx.x * LL + tid] = s;
        }
        __threadfence();
        __syncthreads();
    }

    // ---- last block finalizes loss (512-double region, full tree), resets ctr ----
    unsigned* flag = (unsigned*)(smem + OFF_FLAG);
    if (tid == 0) {
        unsigned done = atomicAdd(&g_ctr, 1u);
        *flag = (done == (unsigned)(nblk - 1)) ? 1u : 0u;
    }
    __syncthreads();
    if (*flag) {
        __threadfence();
        double acc = 0.0;
        for (int b = tid; b < nblk; b += TM) {
            #pragma unroll
            for (int l = 0; l < LL; l++) acc += (double)g_part[(size_t)b * LL + l];
        }
        double* dred = (double*)(smem + OFF_RED);   // 512 doubles = 4096B (in-bounds)
        dred[tid] = acc;
        __syncthreads();
        #pragma unroll
        for (int s = TM / 2; s > 0; s >>= 1) {
            if (tid < s) dred[tid] += dred[tid + s];
            __syncthreads();
        }
        if (tid == 0) {
            if (has_loss) {
                double wgt = (1.0 + (double)RVQ_BETA) / ((double)N * (double)DD * (double)LL);
                out[(size_t)N * DD] = (float)(dred[0] * wgt);
            }
            g_ctr = 0u;
        }
    }
}

extern "C" void kernel_launch(void* const* d_in, const int* in_sizes, int n_in,
                              void* d_out, int out_size) {
    const float* x;
    const float* cb;
    int nx;
    if (n_in >= 2 && in_sizes[0] >= in_sizes[1]) {
        x = (const float*)d_in[0]; cb = (const float*)d_in[1]; nx = in_sizes[0];
    } else {
        x = (const float*)d_in[1]; cb = (const float*)d_in[0]; nx = in_sizes[1];
    }
    int N = nx / DD;
    float* out = (float*)d_out;

    long long need_full = (long long)N * DD + 1 + (long long)N * LL;
    int has_loss = (out_size > (long long)N * DD) ? 1 : 0;
    int has_idx  = (out_size >= need_full) ? 1 : 0;

    int nblk = (N + TM - 1) / TM;      // 256 for N=131072
    if (nblk > MAXBLK_P) nblk = MAXBLK_P;

    cudaFuncSetAttribute(rvq_mma_kernel, cudaFuncAttributeMaxDynamicSharedMemorySize, SMEM_BYTES);

    rvq_prep<<<(LL * NEC + 127) / 128, 128>>>(cb);
    rvq_mma_kernel<<<nblk, TM, SMEM_BYTES>>>(x, cb, out, N, has_loss, has_idx, nblk);
}

// round 16
// speedup vs baseline: 1.2124x; 1.2124x over previous
#include <cuda_runtime.h>
#include <cuda_fp16.h>
#include <cstdint>
#include <cstddef>

// ResidualVectorQuantizer via warp-level fp16 MMA, 3-term exact-enough fp32 GEMM.
// R16: R12 main kernel verbatim (116.0us best) + 4-way-parallel prep kernel
//      (4 threads/code, shuffle cn reduce; was 8.1us serial, now ~2us).
// N x D points, L layers of NE codes (D=32, NE=256, L=4).
// Out (float32): x_q [N*D], mean_loss [1], indices [N*L].

#define DD   32
#define NEC  256
#define LL   4
#define TM   128
#define RVQ_BETA 0.25f
#define MAXBLK_P 8192

// ---- global scratch ----
__device__ uint32_t g_bp[LL * NEC * 32];
__device__ float    g_cn[LL * NEC];          // 0.5*||c||^2
__device__ float    g_part[MAXBLK_P * LL];
__device__ unsigned g_ctr;

// ---- smem map (bytes) ----
#define OFF_B    0          // 256 codes * 128B swizzled = 32768
#define OFF_A    14336      // A rows alias B codes 112..255 (warp-local partition)
#define OFF_R    32768      // residual 128*144 = 18432
#define OFF_CN   51200      // 1024
#define OFF_ARG  52224      // 512
#define OFF_RED  52736      // 1024
#define OFF_FLAG 53760
#define SMEM_BYTES 53888

__device__ __forceinline__ uint32_t packh2(__half a, __half b) {
    __half2 h = __halves2half2(a, b);
    return *(uint32_t*)&h;
}
__device__ __forceinline__ void sp16(float v, __half& h, __half& l) {
    h = __float2half_rn(v);
    l = __float2half_rn(v - __half2float(h));
}
__device__ __forceinline__ uint32_t smem_u32(const void* p) {
    uint32_t a;
    asm("{ .reg .u64 t; cvta.to.shared.u64 t, %1; cvt.u32.u64 %0, t; }" : "=r"(a) : "l"(p));
    return a;
}
__device__ __forceinline__ void cpasync16(uint32_t dst, const void* src) {
    asm volatile("cp.async.cg.shared.global [%0], [%1], 16;" :: "r"(dst), "l"(src));
}
#define CP_COMMIT() asm volatile("cp.async.commit_group;" ::: "memory")
#define CP_WAIT(n)  asm volatile("cp.async.wait_group %0;" :: "n"(n) : "memory")

#define MMA16(C, A0, A1, A2, A3, B0, B1) \
    asm volatile("mma.sync.aligned.m16n8k16.row.col.f32.f16.f16.f32 " \
        "{%0,%1,%2,%3}, {%4,%5,%6,%7}, {%8,%9}, {%0,%1,%2,%3};" \
        : "+f"((C)[0]), "+f"((C)[1]), "+f"((C)[2]), "+f"((C)[3]) \
        : "r"(A0), "r"(A1), "r"(A2), "r"(A3), "r"(B0), "r"(B1))

// ---------------- prep: 4 threads per code; thread kk owns b-frag chunks 2kk,2kk+1 ----
__global__ void rvq_prep(const float* __restrict__ cb) {
    int gid = blockIdx.x * blockDim.x + threadIdx.x;   // 0..4095
    if (gid >= LL * NEC * 4) return;
    int e = gid >> 2;          // code 0..1023
    int kk = gid & 3;          // frag thread-in-group
    const float* row = cb + (size_t)e * DD;

    // thread kk's elements: pairs at {2kk, 2kk+8, 16+2kk, 24+2kk}
    float2 v0 = *(const float2*)(row + 2 * kk);
    float2 v1 = *(const float2*)(row + 2 * kk + 8);
    float2 v2 = *(const float2*)(row + 16 + 2 * kk);
    float2 v3 = *(const float2*)(row + 24 + 2 * kk);

    __half h0, l0, h1, l1, h2, l2, h3, l3, h4, l4, h5, l5, h6, l6, h7, l7;
    sp16(v0.x, h0, l0); sp16(v0.y, h1, l1);
    sp16(v1.x, h2, l2); sp16(v1.y, h3, l3);
    sp16(v2.x, h4, l4); sp16(v2.y, h5, l5);
    sp16(v3.x, h6, l6); sp16(v3.y, h7, l7);

    uint32_t* dst = g_bp + (size_t)e * 32 + 8 * kk;
    *(uint4*)(dst)     = make_uint4(packh2(h0, h1), packh2(h2, h3), packh2(h4, h5), packh2(h6, h7));
    *(uint4*)(dst + 4) = make_uint4(packh2(l0, l1), packh2(l2, l3), packh2(l4, l5), packh2(l6, l7));

    // cn: partial sum of this thread's 8 elems, reduce across the 4-lane group
    float s = 0.f;
    s = fmaf(v0.x, v0.x, s); s = fmaf(v0.y, v0.y, s);
    s = fmaf(v1.x, v1.x, s); s = fmaf(v1.y, v1.y, s);
    s = fmaf(v2.x, v2.x, s); s = fmaf(v2.y, v2.y, s);
    s = fmaf(v3.x, v3.x, s); s = fmaf(v3.y, v3.y, s);
    s += __shfl_xor_sync(0xffffffffu, s, 1);
    s += __shfl_xor_sync(0xffffffffu, s, 2);
    if (kk == 0) g_cn[e] = 0.5f * s;
}

// ---------------- main (R12 verbatim) ----------------
__global__ void __launch_bounds__(TM, 4) rvq_mma_kernel(
    const float* __restrict__ x, const float* __restrict__ cb,
    float* __restrict__ out, int N, int has_loss, int has_idx, int nblk)
{
    extern __shared__ char smem[];
    const uint32_t sbase = smem_u32(smem);
    const int tid = threadIdx.x;
    const int w = tid >> 5;
    const int lane = tid & 31;
    const int q = lane >> 2;
    const int kk = lane & 3;
    const int p = blockIdx.x * TM + tid;
    const bool active = (p < N);

    // ---- one-shot start stagger: desynchronize co-resident blocks ----
    {
        unsigned phase = (blockIdx.x / 148) & 3u;
        if (phase) {
            unsigned long long tgt = (unsigned long long)phase * 4096ull;
            unsigned long long t0 = clock64();
            while ((unsigned long long)(clock64() - t0) < tgt) { }
        }
    }

    char* rrow = smem + OFF_R + tid * 144;

    // init residual rows
    {
        float4* rp = (float4*)rrow;
        if (active) {
            const float4* xr = (const float4*)(x + (size_t)p * DD);
            #pragma unroll
            for (int j = 0; j < 8; j++) rp[j] = xr[j];
        } else {
            float4 z = make_float4(0.f, 0.f, 0.f, 0.f);
            #pragma unroll
            for (int j = 0; j < 8; j++) rp[j] = z;
        }
    }

    const uint32_t bhOff = OFF_B + (uint32_t)q * 128 + (uint32_t)(((2*kk)     ^ q) * 16);
    const uint32_t blOff = OFF_B + (uint32_t)q * 128 + (uint32_t)(((2*kk + 1) ^ q) * 16);

    float tl[LL];
    int bia[LL];

    for (int l = 0; l < LL; l++) {
        __syncthreads();   // entry: ALL warps done reading previous B

        // ---- phase1: cp.async codes 0..111 (+ cn); doesn't touch A region ----
        {
            const char* src = (const char*)(g_bp + (size_t)(l * 256) * 32);
            #pragma unroll
            for (int i = tid; i < 896; i += TM) {
                int code = i >> 3, c = i & 7;
                cpasync16(sbase + OFF_B + code * 128 + ((c ^ (code & 7)) * 16), src + (size_t)i * 16);
            }
            const char* csrc = (const char*)(g_cn + (size_t)l * 256);
            if (tid < 64) cpasync16(sbase + OFF_CN + tid * 16, csrc + (size_t)tid * 16);
            CP_COMMIT();
        }

        // ---- A = -residual fp16 splits -> OFF_A (warp-local rows) ----
        {
            float t[DD];
            const float4* rp = (const float4*)rrow;
            #pragma unroll
            for (int j = 0; j < 8; j++) {
                float4 v = rp[j];
                t[4*j] = v.x; t[4*j+1] = v.y; t[4*j+2] = v.z; t[4*j+3] = v.w;
            }
            char* ap = smem + OFF_A + tid * 144;
            #pragma unroll
            for (int c4 = 0; c4 < 4; c4++) {
                __half h0,l0,h1,l1,h2,l2,h3,l3,h4,l4,h5,l5,h6,l6,h7,l7;
                sp16(-t[2*c4],        h0, l0); sp16(-t[2*c4 + 1],      h1, l1);
                sp16(-t[2*c4 + 8],    h2, l2); sp16(-t[2*c4 + 9],      h3, l3);
                sp16(-t[16 + 2*c4],   h4, l4); sp16(-t[16 + 2*c4 + 1], h5, l5);
                sp16(-t[24 + 2*c4],   h6, l6); sp16(-t[24 + 2*c4 + 1], h7, l7);
                *(uint4*)(ap + c4 * 16)      = make_uint4(packh2(h0,h1), packh2(h2,h3), packh2(h4,h5), packh2(h6,h7));
                *(uint4*)(ap + 64 + c4 * 16) = make_uint4(packh2(l0,l1), packh2(l2,l3), packh2(l4,l5), packh2(l6,l7));
            }
        }
        __syncwarp();

        // ---- A fragments (resident for the layer) ----
        uint4 U0h[2], U1h[2], U0l[2], U1l[2];
        {
            const char* ab = smem + OFF_A + (size_t)(w * 32 + q) * 144 + kk * 16;
            #pragma unroll
            for (int m = 0; m < 2; m++) {
                U0h[m] = *(const uint4*)(ab + (m * 16) * 144);
                U1h[m] = *(const uint4*)(ab + (m * 16 + 8) * 144);
                U0l[m] = *(const uint4*)(ab + (m * 16) * 144 + 64);
                U1l[m] = *(const uint4*)(ab + (m * 16 + 8) * 144 + 64);
            }
        }
        __syncwarp();      // warp's A area reusable

        // ---- phase2: each warp restages the 36 codes aliasing ITS OWN A rows ----
        {
            const char* src = (const char*)(g_bp + (size_t)(l * 256) * 32);
            int base = 896 + 288 * w + lane;
            #pragma unroll
            for (int t = 0; t < 9; t++) {
                int i = base + 32 * t;
                int code = i >> 3, c = i & 7;
                cpasync16(sbase + OFF_B + code * 128 + ((c ^ (code & 7)) * 16), src + (size_t)i * 16);
            }
            CP_COMMIT();
        }

        float best[4];
        int bidx[4];
        #pragma unroll
        for (int j = 0; j < 4; j++) { best[j] = 3.402823466e38f; bidx[j] = 0; }

        auto compute_range = [&](int nt2_lo, int nt2_hi) {
            #pragma unroll 2
            for (int nt2 = nt2_lo; nt2 < nt2_hi; nt2++) {
                const char* p0 = smem + (size_t)nt2 * 2048;
                uint4 BH0 = *(const uint4*)(p0 + bhOff);
                uint4 BL0 = *(const uint4*)(p0 + blOff);
                uint4 BH1 = *(const uint4*)(p0 + 1024 + bhOff);
                uint4 BL1 = *(const uint4*)(p0 + 1024 + blOff);
                float2 cn0 = *(const float2*)(smem + OFF_CN + (size_t)(nt2 * 16 + kk * 2) * 4);
                float2 cn1 = *(const float2*)(smem + OFF_CN + (size_t)(nt2 * 16 + 8 + kk * 2) * 4);

                float C0[2][4], C1[2][4];
                #pragma unroll
                for (int m = 0; m < 2; m++) {
                    C0[m][0] = cn0.x; C0[m][1] = cn0.y; C0[m][2] = cn0.x; C0[m][3] = cn0.y;
                    C1[m][0] = cn1.x; C1[m][1] = cn1.y; C1[m][2] = cn1.x; C1[m][3] = cn1.y;
                }
                #pragma unroll
                for (int m = 0; m < 2; m++) {
                    MMA16(C0[m], U0h[m].x, U1h[m].x, U0h[m].y, U1h[m].y, BH0.x, BH0.y);
                    MMA16(C1[m], U0h[m].x, U1h[m].x, U0h[m].y, U1h[m].y, BH1.x, BH1.y);
                }
                #pragma unroll
                for (int m = 0; m < 2; m++) {
                    MMA16(C0[m], U0h[m].z, U1h[m].z, U0h[m].w, U1h[m].w, BH0.z, BH0.w);
                    MMA16(C1[m], U0h[m].z, U1h[m].z, U0h[m].w, U1h[m].w, BH1.z, BH1.w);
                }
                #pragma unroll
                for (int m = 0; m < 2; m++) {
                    MMA16(C0[m], U0l[m].x, U1l[m].x, U0l[m].y, U1l[m].y, BH0.x, BH0.y);
                    MMA16(C1[m], U0l[m].x, U1l[m].x, U0l[m].y, U1l[m].y, BH1.x, BH1.y);
                }
                #pragma unroll
                for (int m = 0; m < 2; m++) {
                    MMA16(C0[m], U0l[m].z, U1l[m].z, U0l[m].w, U1l[m].w, BH0.z, BH0.w);
                    MMA16(C1[m], U0l[m].z, U1l[m].z, U0l[m].w, U1l[m].w, BH1.z, BH1.w);
                }
                #pragma unroll
                for (int m = 0; m < 2; m++) {
                    MMA16(C0[m], U0h[m].x, U1h[m].x, U0h[m].y, U1h[m].y, BL0.x, BL0.y);
                    MMA16(C1[m], U0h[m].x, U1h[m].x, U0h[m].y, U1h[m].y, BL1.x, BL1.y);
                }
                #pragma unroll
                for (int m = 0; m < 2; m++) {
                    MMA16(C0[m], U0h[m].z, U1h[m].z, U0h[m].w, U1h[m].w, BL0.z, BL0.w);
                    MMA16(C1[m], U0h[m].z, U1h[m].z, U0h[m].w, U1h[m].w, BL1.z, BL1.w);
                }

                int nb0 = (nt2 * 16) + kk * 2;
                int nb1 = nb0 + 8;
                #pragma unroll
                for (int m = 0; m < 2; m++)
                    #pragma unroll
                    for (int hi = 0; hi < 2; hi++) {
                        int jj = m * 2 + hi;
                        {
                            float c0 = C0[m][hi*2], c1 = C0[m][hi*2 + 1];
                            float mn = fminf(c0, c1);
                            int cand = (c1 < c0) ? (nb0 + 1) : nb0;
                            bidx[jj] = (mn < best[jj]) ? cand : bidx[jj];
                            best[jj] = fminf(best[jj], mn);
                        }
                        {
                            float c0 = C1[m][hi*2], c1 = C1[m][hi*2 + 1];
                            float mn = fminf(c0, c1);
                            int cand = (c1 < c0) ? (nb1 + 1) : nb1;
                            bidx[jj] = (mn < best[jj]) ? cand : bidx[jj];
                            best[jj] = fminf(best[jj], mn);
                        }
                    }
            }
        };

        // ---- split-wait: compute codes 0..111 while phase2 lands ----
        CP_WAIT(1);
        __syncthreads();
        compute_range(0, 7);

        CP_WAIT(0);
        __syncthreads();
        compute_range(7, 16);

        // ---- argmin reduce across the 4 kk-lanes of each group ----
        #pragma unroll
        for (int jj = 0; jj < 4; jj++) {
            #pragma unroll
            for (int ofs = 1; ofs <= 2; ofs <<= 1) {
                float ob = __shfl_xor_sync(0xffffffffu, best[jj], ofs);
                int oi = __shfl_xor_sync(0xffffffffu, bidx[jj], ofs);
                if (ob < best[jj] || (ob == best[jj] && oi < bidx[jj])) {
                    best[jj] = ob; bidx[jj] = oi;
                }
            }
        }
        int* argb = (int*)(smem + OFF_ARG);
        if (kk == 0) {
            #pragma unroll
            for (int jj = 0; jj < 4; jj++)
                argb[w * 32 + (jj >> 1) * 16 + (jj & 1) * 8 + q] = bidx[jj];
        }
        __syncwarp();
        int bi = argb[w * 32 + lane];
        bia[l] = bi;

        // ---- residual update + loss; code vector gathered from SMEM (c = h + l) ----
        {
            const char* crow = smem + OFF_B + (size_t)bi * 128;
            const int sw = bi & 7;
            float t[DD];
            {
                const float4* rp = (const float4*)rrow;
                #pragma unroll
                for (int j = 0; j < 8; j++) {
                    float4 v = rp[j];
                    t[4*j] = v.x; t[4*j+1] = v.y; t[4*j+2] = v.z; t[4*j+3] = v.w;
                }
            }
            float ls = 0.f;
            #pragma unroll
            for (int kkc = 0; kkc < 4; kkc++) {
                uint4 H = *(const uint4*)(crow + (((2*kkc)     ^ sw) * 16));
                uint4 L = *(const uint4*)(crow + (((2*kkc + 1) ^ sw) * 16));
                const uint32_t hw[4] = {H.x, H.y, H.z, H.w};
                const uint32_t lw[4] = {L.x, L.y, L.z, L.w};
                const int baseix[4] = {2*kkc, 2*kkc + 8, 16 + 2*kkc, 24 + 2*kkc};
                #pragma unroll
                for (int t2 = 0; t2 < 4; t2++) {
                    float2 hf = __half22float2(*(const __half2*)&hw[t2]);
                    float2 lf = __half22float2(*(const __half2*)&lw[t2]);
                    float cx = hf.x + lf.x;
                    float cy = hf.y + lf.y;
                    int b0 = baseix[t2];
                    float t0, xres;
                    t0 = cx - t[b0];     ls = fmaf(t0, t0, ls); xres = t[b0]     + t0; t[b0]     = t[b0]     - xres;
                    t0 = cy - t[b0 + 1]; ls = fmaf(t0, t0, ls); xres = t[b0 + 1] + t0; t[b0 + 1] = t[b0 + 1] - xres;
                }
            }
            {
                float4* rp = (float4*)rrow;
                #pragma unroll
                for (int j = 0; j < 8; j++)
                    rp[j] = make_float4(t[4*j], t[4*j+1], t[4*j+2], t[4*j+3]);
            }
            tl[l] = active ? ls : 0.f;
        }
    }

    // ---- outputs ----
    if (active) {
        const float4* xr = (const float4*)(x + (size_t)p * DD);
        float4* qo = (float4*)(out + (size_t)p * DD);
        const float4* rp = (const float4*)rrow;
        #pragma unroll
        for (int j = 0; j < 8; j++) {
            float4 v = xr[j];
            float4 rv = rp[j];
            float4 qv;
            qv.x = v.x - rv.x; qv.y = v.y - rv.y;
            qv.z = v.z - rv.z; qv.w = v.w - rv.w;
            qo[j] = qv;
        }
        if (has_idx) {
            float* oi = out + (size_t)N * DD + (has_loss ? 1 : 0) + (size_t)p * LL;
            #pragma unroll
            for (int l = 0; l < LL; l++) oi[l] = (float)bia[l];
        }
    }

    // ---- per-block loss partials: warp shuffle reduce (deterministic order) ----
    {
        float* wsum = (float*)(smem + OFF_RED);
        #pragma unroll
        for (int l = 0; l < LL; l++) {
            float v = tl[l];
            v += __shfl_xor_sync(0xffffffffu, v, 16);
            v += __shfl_xor_sync(0xffffffffu, v, 8);
            v += __shfl_xor_sync(0xffffffffu, v, 4);
            v += __shfl_xor_sync(0xffffffffu, v, 2);
            v += __shfl_xor_sync(0xffffffffu, v, 1);
            if (lane == 0) wsum[w * LL + l] = v;
        }
        __syncthreads();
        if (tid < LL) {
            float s = ((wsum[tid] + wsum[LL + tid]) + (wsum[2*LL + tid] + wsum[3*LL + tid]));
            g_part[(size_t)blockIdx.x * LL + tid] = s;
        }
        __threadfence();
        __syncthreads();
    }

    // ---- last block finalizes loss, resets ctr ----
    unsigned* flag = (unsigned*)(smem + OFF_FLAG);
    if (tid == 0) {
        unsigned done = atomicAdd(&g_ctr, 1u);
        *flag = (done == (unsigned)(nblk - 1)) ? 1u : 0u;
    }
    __syncthreads();
    if (*flag) {
        __threadfence();
        double acc = 0.0;
        for (int b = tid; b < nblk; b += TM) {
            #pragma unroll
            for (int l = 0; l < LL; l++) acc += (double)g_part[(size_t)b * LL + l];
        }
        double* dred = (double*)(smem + OFF_RED);
        dred[tid] = acc;
        __syncthreads();
        #pragma unroll
        for (int s = TM / 2; s > 0; s >>= 1) {
            if (tid < s) dred[tid] += dred[tid + s];
            __syncthreads();
        }
        if (tid == 0) {
            if (has_loss) {
                double wgt = (1.0 + (double)RVQ_BETA) / ((double)N * (double)DD * (double)LL);
                out[(size_t)N * DD] = (float)(dred[0] * wgt);
            }
            g_ctr = 0u;
        }
    }
}

extern "C" void kernel_launch(void* const* d_in, const int* in_sizes, int n_in,
                              void* d_out, int out_size) {
    const float* x;
    const float* cb;
    int nx;
    if (n_in >= 2 && in_sizes[0] >= in_sizes[1]) {
        x = (const float*)d_in[0]; cb = (const float*)d_in[1]; nx = in_sizes[0];
    } else {
        x = (const float*)d_in[1]; cb = (const float*)d_in[0]; nx = in_sizes[1];
    }
    int N = nx / DD;
    float* out = (float*)d_out;

    long long need_full = (long long)N * DD + 1 + (long long)N * LL;
    int has_loss = (out_size > (long long)N * DD) ? 1 : 0;
    int has_idx  = (out_size >= need_full) ? 1 : 0;

    int nblk = (N + TM - 1) / TM;
    if (nblk > MAXBLK_P) nblk = MAXBLK_P;

    cudaFuncSetAttribute(rvq_mma_kernel, cudaFuncAttributeMaxDynamicSharedMemorySize, SMEM_BYTES);

    rvq_prep<<<(LL * NEC * 4 + 127) / 128, 128>>>(cb);
    rvq_mma_kernel<<<nblk, TM, SMEM_BYTES>>>(x, cb, out, N, has_loss, has_idx, nblk);
}